// round 1
// baseline (speedup 1.0000x reference)
#include <cuda_runtime.h>

#define BATCH 16
#define LOC_C 31
#define FEAT (32*32*31)   // 31744
#define BN_EPS 1e-3f

__device__ __align__(16) float g_buf1[16*128*128*8];   // conv1+pool out
__device__ __align__(16) float g_buf2[16*64*64*16];    // conv2+pool out
__device__ __align__(16) float g_xint[16*32*32*31];    // conv3+pool out (x_intermediate)
__device__ float g_f1[16*64];                          // dense1 accumulator
__device__ float g_theta[16*6];

// ---------------- conv1 (1->8) + relu + maxpool2 ----------------
// out pooled (16,128,128,8). block 16x16 pooled pixels, grid (8,8,16)
__global__ void conv1pool_k(const float* __restrict__ x,
                            const float* __restrict__ k,
                            const float* __restrict__ bias)
{
    __shared__ float sp[34*36];
    __shared__ float sk[72];
    __shared__ float sb[8];
    int b = blockIdx.z;
    int px0 = blockIdx.x*16, py0 = blockIdx.y*16;
    int tid = threadIdx.y*16+threadIdx.x;
    int iy0 = py0*2-1, ix0 = px0*2-1;
    for (int idx = tid; idx < 34*34; idx += 256) {
        int yy = idx/34, xx = idx-yy*34;
        int gy = iy0+yy, gx = ix0+xx;
        float v = 0.f;
        if ((unsigned)gy < 256u && (unsigned)gx < 256u) v = x[(b*256+gy)*256+gx];
        sp[yy*36+xx] = v;
    }
    if (tid < 72) sk[tid] = k[tid];
    if (tid < 8)  sb[tid] = bias[tid];
    __syncthreads();
    int tx = threadIdx.x, ty = threadIdx.y;
    float p[4][4];
    #pragma unroll
    for (int r=0;r<4;r++)
      #pragma unroll
      for (int c=0;c<4;c++)
        p[r][c] = sp[(ty*2+r)*36 + tx*2+c];
    float o[8];
    #pragma unroll
    for (int co=0;co<8;co++){
        float w[9];
        #pragma unroll
        for (int t=0;t<9;t++) w[t]=sk[t*8+co];
        float s00=0.f,s01=0.f,s10=0.f,s11=0.f;
        #pragma unroll
        for (int r=0;r<3;r++)
          #pragma unroll
          for (int c=0;c<3;c++){
            float wv = w[r*3+c];
            s00 += p[r][c]*wv;
            s01 += p[r][c+1]*wv;
            s10 += p[r+1][c]*wv;
            s11 += p[r+1][c+1]*wv;
          }
        float m = fmaxf(fmaxf(s00,s01),fmaxf(s10,s11)) + sb[co];
        o[co] = fmaxf(m, 0.f);
    }
    int py = py0+ty, px = px0+tx;
    float4* outp = (float4*)&g_buf1[((b*128+py)*128+px)*8];
    outp[0] = make_float4(o[0],o[1],o[2],o[3]);
    outp[1] = make_float4(o[4],o[5],o[6],o[7]);
}

// ---------------- conv2 (8->16) + relu + maxpool2 ----------------
// out pooled (16,64,64,16). block 16x16 pooled pixels, grid (4,4,16)
__global__ void __launch_bounds__(256) conv2pool_k(const float* __restrict__ k,
                                                   const float* __restrict__ bias)
{
    __shared__ float sp[8][34*36];  // planar, padded rows
    __shared__ float sw[1152];
    __shared__ float sb[16];
    int b = blockIdx.z;
    int px0 = blockIdx.x*16, py0 = blockIdx.y*16;
    int tid = threadIdx.y*16+threadIdx.x;
    int iy0 = py0*2-1, ix0 = px0*2-1;
    for (int idx=tid; idx<34*34*2; idx+=256){
        int q = idx & 1; int pix = idx >> 1;
        int yy = pix/34, xx = pix - yy*34;
        int gy = iy0+yy, gx = ix0+xx;
        float4 v = make_float4(0.f,0.f,0.f,0.f);
        if ((unsigned)gy<128u && (unsigned)gx<128u)
            v = *(const float4*)&g_buf1[((b*128+gy)*128+gx)*8 + q*4];
        int off = yy*36+xx;
        sp[q*4+0][off]=v.x; sp[q*4+1][off]=v.y; sp[q*4+2][off]=v.z; sp[q*4+3][off]=v.w;
    }
    for (int idx=tid; idx<1152; idx+=256) sw[idx]=k[idx];
    if (tid<16) sb[tid]=bias[tid];
    __syncthreads();
    int tx=threadIdx.x, ty=threadIdx.y;
    float acc[4][16];
    #pragma unroll
    for (int p_=0;p_<4;p_++)
      #pragma unroll
      for(int co=0;co<16;co++) acc[p_][co]=0.f;

    #pragma unroll 1
    for (int t=0;t<9;t++){
        int dy=t/3, dx=t-3*dy;
        #pragma unroll 1
        for (int ci=0;ci<8;ci++){
            float w[16];
            #pragma unroll
            for (int co=0;co<16;co++) w[co]=sw[(t*8+ci)*16+co];
            const float* pl = sp[ci];
            int base = (ty*2+dy)*36 + tx*2+dx;
            float v00 = pl[base];
            float v01 = pl[base+1];
            float v10 = pl[base+36];
            float v11 = pl[base+37];
            #pragma unroll
            for (int co=0;co<16;co++){
                acc[0][co] += v00*w[co];
                acc[1][co] += v01*w[co];
                acc[2][co] += v10*w[co];
                acc[3][co] += v11*w[co];
            }
        }
    }
    int py=py0+ty, px=px0+tx;
    float* outp = &g_buf2[((b*64+py)*64+px)*16];
    #pragma unroll
    for (int co=0;co<16;co++){
        float m = fmaxf(fmaxf(acc[0][co],acc[1][co]),fmaxf(acc[2][co],acc[3][co]))+sb[co];
        outp[co] = fmaxf(m,0.f);
    }
}

// ---------------- conv3 (16->31) + relu + maxpool2 ----------------
// out pooled (16,32,32,31). block = 64 pixels (8x8) x 4 co-groups, grid (4,4,16)
__global__ void __launch_bounds__(256) conv3pool_k(const float* __restrict__ k,
                                                   const float* __restrict__ bias)
{
    __shared__ float sp[16][18*20];
    __shared__ float sw[9*16*32];   // co padded to 32
    __shared__ float sb[32];
    int b = blockIdx.z;
    int px0 = blockIdx.x*8, py0 = blockIdx.y*8;
    int tid = threadIdx.x;
    int iy0 = py0*2-1, ix0 = px0*2-1;
    for (int idx=tid; idx<18*18*4; idx+=256){
        int q = idx & 3; int pix = idx >> 2;
        int yy=pix/18, xx=pix-yy*18;
        int gy=iy0+yy, gx=ix0+xx;
        float4 v=make_float4(0.f,0.f,0.f,0.f);
        if ((unsigned)gy<64u && (unsigned)gx<64u)
            v = *(const float4*)&g_buf2[((b*64+gy)*64+gx)*16 + q*4];
        int off=yy*20+xx;
        sp[q*4+0][off]=v.x; sp[q*4+1][off]=v.y; sp[q*4+2][off]=v.z; sp[q*4+3][off]=v.w;
    }
    for (int idx=tid; idx<9*16*32; idx+=256){
        int co = idx & 31; int tc = idx >> 5;
        sw[idx] = (co<31) ? k[tc*31+co] : 0.f;
    }
    if (tid<32) sb[tid] = (tid<31)? bias[tid] : 0.f;
    __syncthreads();
    int g = tid>>6; int pid = tid&63; int tx=pid&7, ty=pid>>3;
    int cobase = g*8;
    float acc[4][8];
    #pragma unroll
    for (int p_=0;p_<4;p_++)
      #pragma unroll
      for (int kk=0;kk<8;kk++) acc[p_][kk]=0.f;

    #pragma unroll 1
    for (int t=0;t<9;t++){
        int dy=t/3, dx=t-3*dy;
        #pragma unroll 1
        for (int ci=0;ci<16;ci++){
            float w[8];
            #pragma unroll
            for (int kk=0;kk<8;kk++) w[kk]=sw[(t*16+ci)*32+cobase+kk];
            const float* pl = sp[ci];
            int base=(ty*2+dy)*20+tx*2+dx;
            float v00=pl[base], v01=pl[base+1], v10=pl[base+20], v11=pl[base+21];
            #pragma unroll
            for (int kk=0;kk<8;kk++){
                acc[0][kk]+=v00*w[kk]; acc[1][kk]+=v01*w[kk];
                acc[2][kk]+=v10*w[kk]; acc[3][kk]+=v11*w[kk];
            }
        }
    }
    int py=py0+ty, px=px0+tx;
    float* outp = &g_xint[((b*32+py)*32+px)*31];
    #pragma unroll
    for (int kk=0;kk<8;kk++){
        int co=cobase+kk;
        if (co<31){
            float m = fmaxf(fmaxf(acc[0][kk],acc[1][kk]),fmaxf(acc[2][kk],acc[3][kk]))+sb[co];
            outp[co]=fmaxf(m,0.f);
        }
    }
}

// ---------------- dense1: BN + (16x31744)@(31744x64), split-K ----------------
__global__ void zero_f1_k(){
    int t = blockIdx.x*blockDim.x+threadIdx.x;
    if (t < 16*64) g_f1[t]=0.f;
}

__global__ void __launch_bounds__(256) dense1_k(const float* __restrict__ gamma,
                                                const float* __restrict__ beta,
                                                const float* __restrict__ mean,
                                                const float* __restrict__ var,
                                                const float* __restrict__ Wd)
{
    __shared__ float fsm[512*17];   // fsm[il*17 + b]
    int i0 = blockIdx.x*512;
    int tid = threadIdx.x;
    for (int idx=tid; idx<512*16; idx+=256){
        int bb = idx>>9; int il = idx & 511;
        int i = i0+il;
        float xv = g_xint[bb*FEAT + i];
        float fv = (xv - mean[i]) * rsqrtf(var[i]+BN_EPS) * gamma[i] + beta[i];
        fsm[il*17+bb] = fv;
    }
    __syncthreads();
    int j = tid & 63, bg = tid>>6;   // 64 j x 4 b-groups
    float a0=0.f,a1=0.f,a2=0.f,a3=0.f;
    #pragma unroll 4
    for (int il=0; il<512; il++){
        float w = Wd[(i0+il)*64 + j];
        const float* f = &fsm[il*17 + bg*4];
        a0 += f[0]*w; a1 += f[1]*w; a2 += f[2]*w; a3 += f[3]*w;
    }
    atomicAdd(&g_f1[(bg*4+0)*64+j], a0);
    atomicAdd(&g_f1[(bg*4+1)*64+j], a1);
    atomicAdd(&g_f1[(bg*4+2)*64+j], a2);
    atomicAdd(&g_f1[(bg*4+3)*64+j], a3);
}

// ---------------- dense2 + dense3 -> theta ----------------
__global__ void denserest_k(const float* __restrict__ d1b,
                            const float* __restrict__ d2k, const float* __restrict__ d2b,
                            const float* __restrict__ d3k, const float* __restrict__ d3b)
{
    __shared__ float h1[64], h2[96];
    int b=blockIdx.x, t=threadIdx.x;  // 96 threads
    if (t<64) h1[t] = fmaxf(g_f1[b*64+t] + d1b[t], 0.f);
    __syncthreads();
    float s = d2b[t];
    for (int i=0;i<64;i++) s += h1[i]*d2k[i*96+t];
    h2[t] = fmaxf(s,0.f);
    __syncthreads();
    if (t<6){
        float s2 = d3b[t];
        for (int i=0;i<96;i++) s2 += h2[i]*d3k[i*6+t];
        g_theta[b*6+t] = s2;
    }
}

// ---------------- affine grid + nearest-resize + concat + bilinear + leaky ----------------
// warp = one output pixel, lane = channel (0 from x, 1..31 from x_int cell)
__global__ void __launch_bounds__(256) sampler_k(const float* __restrict__ x,
                                                 float* __restrict__ out)
{
    int pix = blockIdx.x*8 + (threadIdx.x>>5);
    int lane = threadIdx.x & 31;
    int b = pix >> 16;
    int h = (pix >> 8) & 255;
    int w = pix & 255;
    const float* th = &g_theta[b*6];
    float gx = (float)w/255.f*2.f - 1.f;
    float gy = (float)h/255.f*2.f - 1.f;
    // theta layout (2x3 row-major): [a00 a01 t0 a10 a11 t1], tg_d = sum_c grid_c*A[c][d] + t[d]
    float tx = gx*th[0] + gy*th[3] + th[2];
    float ty = gx*th[1] + gy*th[4] + th[5];
    float xf = 0.5f*((tx+1.f)*255.f);
    float yf = 0.5f*((ty+1.f)*255.f);
    float x0f = floorf(xf), y0f = floorf(yf);
    float x1f = x0f+1.f,  y1f = y0f+1.f;
    float x0c = fminf(fmaxf(x0f,0.f),255.f);
    float x1c = fminf(fmaxf(x1f,0.f),255.f);
    float y0c = fminf(fmaxf(y0f,0.f),255.f);
    float y1c = fminf(fmaxf(y1f,0.f),255.f);
    float wa=(x1c-xf)*(y1c-yf), wb=(x1c-xf)*(yf-y0c);
    float wc=(xf-x0c)*(y1c-yf), wd=(xf-x0c)*(yf-y0c);
    int xi0=(int)x0c, xi1=(int)x1c, yi0=(int)y0c, yi1=(int)y1c;
    float val;
    if (lane == 0){
        const float* xb = x + b*65536;
        val = wa*xb[yi0*256+xi0] + wb*xb[yi1*256+xi0]
            + wc*xb[yi0*256+xi1] + wd*xb[yi1*256+xi1];
    } else {
        int c = lane-1;
        const float* xb = &g_xint[b*(32*32*31)];
        int ya=yi0>>3, yb=yi1>>3, xa=xi0>>3, xn=xi1>>3;
        float Ia = xb[(ya*32+xa)*31+c];
        float Ib = (yb==ya) ? Ia : xb[(yb*32+xa)*31+c];
        float Ic = (xn==xa) ? Ia : xb[(ya*32+xn)*31+c];
        float Id = (xn==xa) ? Ib : ((yb==ya) ? Ic : xb[(yb*32+xn)*31+c]);
        val = wa*Ia + wb*Ib + wc*Ic + wd*Id;
    }
    val = (val >= 0.f) ? val : 0.1f*val;
    out[pix*32 + lane] = val;
}

extern "C" void kernel_launch(void* const* d_in, const int* in_sizes, int n_in,
                              void* d_out, int out_size)
{
    const float* x   = (const float*)d_in[0];
    const float* c1k = (const float*)d_in[1];
    const float* c1b = (const float*)d_in[2];
    const float* c2k = (const float*)d_in[3];
    const float* c2b = (const float*)d_in[4];
    const float* c3k = (const float*)d_in[5];
    const float* c3b = (const float*)d_in[6];
    const float* bng = (const float*)d_in[7];
    const float* bnb = (const float*)d_in[8];
    const float* bnm = (const float*)d_in[9];
    const float* bnv = (const float*)d_in[10];
    const float* d1k = (const float*)d_in[11];
    const float* d1b = (const float*)d_in[12];
    const float* d2k = (const float*)d_in[13];
    const float* d2b = (const float*)d_in[14];
    const float* d3k = (const float*)d_in[15];
    const float* d3b = (const float*)d_in[16];
    float* out = (float*)d_out;

    dim3 t16(16,16);
    conv1pool_k<<<dim3(8,8,16), t16>>>(x, c1k, c1b);
    conv2pool_k<<<dim3(4,4,16), t16>>>(c2k, c2b);
    conv3pool_k<<<dim3(4,4,16), 256>>>(c3k, c3b);
    zero_f1_k<<<4,256>>>();
    dense1_k<<<62,256>>>(bng, bnb, bnm, bnv, d1k);
    denserest_k<<<16,96>>>(d1b, d2k, d2b, d3k, d3b);
    sampler_k<<<16*256*256/8, 256>>>(x, out);
}

// round 2
// speedup vs baseline: 1.5055x; 1.5055x over previous
#include <cuda_runtime.h>

#define FEAT (32*32*31)   // 31744
#define BN_EPS 1e-3f

__device__ __align__(16) float g_buf1[16*128*128*8];   // conv1+pool out
__device__ __align__(16) float g_buf2[16*64*64*16];    // conv2+pool out
__device__ __align__(16) float g_xintp[16*32*32*32];   // conv3+pool out, padded: slot 1+c
__device__ __align__(16) float g_f1p[62*16*64];        // dense1 partials
__device__ __align__(16) float g_theta[16*8];          // theta padded to 8/b

// ---- f32x2 helpers ----
#define FFMA2(d,a,b,c) asm("fma.rn.f32x2 %0,%1,%2,%3;" : "=l"(d) : "l"(a), "l"(b), "l"(c))
#define PK2(d,lo,hi)   asm("mov.b64 %0,{%1,%2};" : "=l"(d) : "r"(__float_as_uint(lo)), "r"(__float_as_uint(hi)))
#define UNPK2(lo,hi,v) do { unsigned _l,_h; asm("mov.b64 {%0,%1},%2;" : "=r"(_l), "=r"(_h) : "l"(v)); lo=__uint_as_float(_l); hi=__uint_as_float(_h); } while(0)

// ---------------- conv1 (1->8) + relu + maxpool2 ----------------
__global__ void conv1pool_k(const float* __restrict__ x,
                            const float* __restrict__ k,
                            const float* __restrict__ bias)
{
    __shared__ float sp[34*36];
    __shared__ float sk[72];
    __shared__ float sb[8];
    int b = blockIdx.z;
    int px0 = blockIdx.x*16, py0 = blockIdx.y*16;
    int tid = threadIdx.y*16+threadIdx.x;
    int iy0 = py0*2-1, ix0 = px0*2-1;
    for (int idx = tid; idx < 34*34; idx += 256) {
        int yy = idx/34, xx = idx-yy*34;
        int gy = iy0+yy, gx = ix0+xx;
        float v = 0.f;
        if ((unsigned)gy < 256u && (unsigned)gx < 256u) v = x[(b*256+gy)*256+gx];
        sp[yy*36+xx] = v;
    }
    if (tid < 72) sk[tid] = k[tid];
    if (tid < 8)  sb[tid] = bias[tid];
    __syncthreads();
    int tx = threadIdx.x, ty = threadIdx.y;
    float p[4][4];
    #pragma unroll
    for (int r=0;r<4;r++)
      #pragma unroll
      for (int c=0;c<4;c++)
        p[r][c] = sp[(ty*2+r)*36 + tx*2+c];
    float o[8];
    #pragma unroll
    for (int co=0;co<8;co++){
        float w[9];
        #pragma unroll
        for (int t=0;t<9;t++) w[t]=sk[t*8+co];
        float s00=0.f,s01=0.f,s10=0.f,s11=0.f;
        #pragma unroll
        for (int r=0;r<3;r++)
          #pragma unroll
          for (int c=0;c<3;c++){
            float wv = w[r*3+c];
            s00 += p[r][c]*wv;
            s01 += p[r][c+1]*wv;
            s10 += p[r+1][c]*wv;
            s11 += p[r+1][c+1]*wv;
          }
        float m = fmaxf(fmaxf(s00,s01),fmaxf(s10,s11)) + sb[co];
        o[co] = fmaxf(m, 0.f);
    }
    int py = py0+ty, px = px0+tx;
    float4* outp = (float4*)&g_buf1[((b*128+py)*128+px)*8];
    outp[0] = make_float4(o[0],o[1],o[2],o[3]);
    outp[1] = make_float4(o[4],o[5],o[6],o[7]);
}

// ---------------- conv2 (8->16) + relu + maxpool2 (f32x2) ----------------
__global__ void __launch_bounds__(256) conv2pool_k(const float* __restrict__ k,
                                                   const float* __restrict__ bias)
{
    __shared__ float sp[8][34*36];
    __shared__ __align__(8) float sw[1152];
    __shared__ float sb[16];
    int b = blockIdx.z;
    int px0 = blockIdx.x*16, py0 = blockIdx.y*16;
    int tid = threadIdx.y*16+threadIdx.x;
    int iy0 = py0*2-1, ix0 = px0*2-1;
    for (int idx=tid; idx<34*34*2; idx+=256){
        int q = idx & 1; int pix = idx >> 1;
        int yy = pix/34, xx = pix - yy*34;
        int gy = iy0+yy, gx = ix0+xx;
        float4 v = make_float4(0.f,0.f,0.f,0.f);
        if ((unsigned)gy<128u && (unsigned)gx<128u)
            v = *(const float4*)&g_buf1[((b*128+gy)*128+gx)*8 + q*4];
        int off = yy*36+xx;
        sp[q*4+0][off]=v.x; sp[q*4+1][off]=v.y; sp[q*4+2][off]=v.z; sp[q*4+3][off]=v.w;
    }
    for (int idx=tid; idx<1152; idx+=256) sw[idx]=k[idx];
    if (tid<16) sb[tid]=bias[tid];
    __syncthreads();
    int tx=threadIdx.x, ty=threadIdx.y;
    unsigned long long acc2[4][8];
    #pragma unroll
    for (int p_=0;p_<4;p_++)
      #pragma unroll
      for(int kk=0;kk<8;kk++) acc2[p_][kk]=0ull;

    #pragma unroll 1
    for (int t=0;t<9;t++){
        int dy=t/3, dx=t-3*dy;
        #pragma unroll 1
        for (int ci=0;ci<8;ci++){
            const unsigned long long* wp = (const unsigned long long*)&sw[(t*8+ci)*16];
            unsigned long long w2[8];
            #pragma unroll
            for (int kk=0;kk<8;kk++) w2[kk]=wp[kk];
            const float* pl = sp[ci];
            int base = (ty*2+dy)*36 + tx*2+dx;
            float v00 = pl[base];
            float v01 = pl[base+1];
            float v10 = pl[base+36];
            float v11 = pl[base+37];
            unsigned long long p00,p01,p10,p11;
            PK2(p00,v00,v00); PK2(p01,v01,v01); PK2(p10,v10,v10); PK2(p11,v11,v11);
            #pragma unroll
            for (int kk=0;kk<8;kk++){
                FFMA2(acc2[0][kk], p00, w2[kk], acc2[0][kk]);
                FFMA2(acc2[1][kk], p01, w2[kk], acc2[1][kk]);
                FFMA2(acc2[2][kk], p10, w2[kk], acc2[2][kk]);
                FFMA2(acc2[3][kk], p11, w2[kk], acc2[3][kk]);
            }
        }
    }
    int py=py0+ty, px=px0+tx;
    float* outp = &g_buf2[((b*64+py)*64+px)*16];
    #pragma unroll
    for (int kk=0;kk<8;kk++){
        float a0,a1,b0,b1,c0,c1,d0,d1;
        UNPK2(a0,a1,acc2[0][kk]); UNPK2(b0,b1,acc2[1][kk]);
        UNPK2(c0,c1,acc2[2][kk]); UNPK2(d0,d1,acc2[3][kk]);
        float m0 = fmaxf(fmaxf(a0,b0),fmaxf(c0,d0))+sb[kk*2+0];
        float m1 = fmaxf(fmaxf(a1,b1),fmaxf(c1,d1))+sb[kk*2+1];
        outp[kk*2+0] = fmaxf(m0,0.f);
        outp[kk*2+1] = fmaxf(m1,0.f);
    }
}

// ---------------- conv3 (16->31) + relu + maxpool2 (f32x2, padded out) ----------------
__global__ void __launch_bounds__(256) conv3pool_k(const float* __restrict__ k,
                                                   const float* __restrict__ bias)
{
    __shared__ float sp[16][18*20];
    __shared__ __align__(8) float sw[9*16*32];   // co padded to 32
    __shared__ float sb[32];
    int b = blockIdx.z;
    int px0 = blockIdx.x*8, py0 = blockIdx.y*8;
    int tid = threadIdx.x;
    int iy0 = py0*2-1, ix0 = px0*2-1;
    for (int idx=tid; idx<18*18*4; idx+=256){
        int q = idx & 3; int pix = idx >> 2;
        int yy=pix/18, xx=pix-yy*18;
        int gy=iy0+yy, gx=ix0+xx;
        float4 v=make_float4(0.f,0.f,0.f,0.f);
        if ((unsigned)gy<64u && (unsigned)gx<64u)
            v = *(const float4*)&g_buf2[((b*64+gy)*64+gx)*16 + q*4];
        int off=yy*20+xx;
        sp[q*4+0][off]=v.x; sp[q*4+1][off]=v.y; sp[q*4+2][off]=v.z; sp[q*4+3][off]=v.w;
    }
    for (int idx=tid; idx<9*16*32; idx+=256){
        int co = idx & 31; int tc = idx >> 5;
        sw[idx] = (co<31) ? k[tc*31+co] : 0.f;
    }
    if (tid<32) sb[tid] = (tid<31)? bias[tid] : 0.f;
    __syncthreads();
    int g = tid>>6; int pid = tid&63; int tx=pid&7, ty=pid>>3;
    int cobase = g*8;
    unsigned long long acc2[4][4];
    #pragma unroll
    for (int p_=0;p_<4;p_++)
      #pragma unroll
      for (int kk=0;kk<4;kk++) acc2[p_][kk]=0ull;

    #pragma unroll 1
    for (int t=0;t<9;t++){
        int dy=t/3, dx=t-3*dy;
        #pragma unroll 1
        for (int ci=0;ci<16;ci++){
            const unsigned long long* wp = (const unsigned long long*)&sw[(t*16+ci)*32+cobase];
            unsigned long long w2[4];
            #pragma unroll
            for (int kk=0;kk<4;kk++) w2[kk]=wp[kk];
            const float* pl = sp[ci];
            int base=(ty*2+dy)*20+tx*2+dx;
            float v00=pl[base], v01=pl[base+1], v10=pl[base+20], v11=pl[base+21];
            unsigned long long p00,p01,p10,p11;
            PK2(p00,v00,v00); PK2(p01,v01,v01); PK2(p10,v10,v10); PK2(p11,v11,v11);
            #pragma unroll
            for (int kk=0;kk<4;kk++){
                FFMA2(acc2[0][kk], p00, w2[kk], acc2[0][kk]);
                FFMA2(acc2[1][kk], p01, w2[kk], acc2[1][kk]);
                FFMA2(acc2[2][kk], p10, w2[kk], acc2[2][kk]);
                FFMA2(acc2[3][kk], p11, w2[kk], acc2[3][kk]);
            }
        }
    }
    int py=py0+ty, px=px0+tx;
    float* outp = &g_xintp[((b*32+py)*32+px)*32];   // padded: slot 1+co
    #pragma unroll
    for (int kk=0;kk<4;kk++){
        float a0,a1,b0,b1,c0,c1,d0,d1;
        UNPK2(a0,a1,acc2[0][kk]); UNPK2(b0,b1,acc2[1][kk]);
        UNPK2(c0,c1,acc2[2][kk]); UNPK2(d0,d1,acc2[3][kk]);
        int co0 = cobase+kk*2, co1 = cobase+kk*2+1;
        float m0 = fmaxf(fmaxf(a0,b0),fmaxf(c0,d0))+sb[co0];
        float m1 = fmaxf(fmaxf(a1,b1),fmaxf(c1,d1))+sb[co1];
        if (co0<31) outp[1+co0] = fmaxf(m0,0.f);
        if (co1<31) outp[1+co1] = fmaxf(m1,0.f);
    }
}

// ---------------- dense1: BN + (16x31744)@(31744x64), split-K partials ----------------
__global__ void __launch_bounds__(256) dense1_k(const float* __restrict__ gamma,
                                                const float* __restrict__ beta,
                                                const float* __restrict__ mean,
                                                const float* __restrict__ var,
                                                const float* __restrict__ Wd)
{
    __shared__ float fsm[512*17];   // fsm[il*17 + b]
    int i0 = blockIdx.x*512;
    int tid = threadIdx.x;
    for (int idx=tid; idx<512*16; idx+=256){
        int bb = idx>>9; int il = idx & 511;
        int i = i0+il;
        int cell = i/31; int c = i - cell*31;
        float xv = g_xintp[bb*32768 + cell*32 + 1 + c];
        float fv = (xv - mean[i]) * rsqrtf(var[i]+BN_EPS) * gamma[i] + beta[i];
        fsm[il*17+bb] = fv;
    }
    __syncthreads();
    int j = tid & 63, bg = tid>>6;
    float a0=0.f,a1=0.f,a2=0.f,a3=0.f;
    #pragma unroll 4
    for (int il=0; il<512; il++){
        float w = Wd[(i0+il)*64 + j];
        const float* f = &fsm[il*17 + bg*4];
        a0 += f[0]*w; a1 += f[1]*w; a2 += f[2]*w; a3 += f[3]*w;
    }
    float* o = &g_f1p[blockIdx.x*1024];
    o[(bg*4+0)*64+j] = a0;
    o[(bg*4+1)*64+j] = a1;
    o[(bg*4+2)*64+j] = a2;
    o[(bg*4+3)*64+j] = a3;
}

// ---------------- reduce partials + dense2 + dense3 -> theta ----------------
__global__ void denserest_k(const float* __restrict__ d1b,
                            const float* __restrict__ d2k, const float* __restrict__ d2b,
                            const float* __restrict__ d3k, const float* __restrict__ d3b)
{
    __shared__ float h1[64], h2[96];
    int b=blockIdx.x, t=threadIdx.x;  // 96 threads
    if (t<64){
        float s = 0.f;
        #pragma unroll 2
        for (int p=0;p<62;p++) s += g_f1p[p*1024 + b*64 + t];
        h1[t] = fmaxf(s + d1b[t], 0.f);
    }
    __syncthreads();
    float s = d2b[t];
    for (int i=0;i<64;i++) s += h1[i]*d2k[i*96+t];
    h2[t] = fmaxf(s,0.f);
    __syncthreads();
    if (t<6){
        float s2 = d3b[t];
        for (int i=0;i<96;i++) s2 += h2[i]*d3k[i*6+t];
        g_theta[b*8+t] = s2;
    }
}

// ---------------- grid + resize + concat + bilinear + leaky (vectorized) ----------------
// thread = (pixel, channel-quad q in 0..7); block = 32 pixels
__global__ void __launch_bounds__(256) sampler_k(const float* __restrict__ x,
                                                 float* __restrict__ out)
{
    int tid = threadIdx.x;
    int pix = blockIdx.x*32 + (tid>>3);
    int q = tid & 7;
    int b = pix >> 16;
    int h = (pix >> 8) & 255;
    int w = pix & 255;
    float4 t03 = *(const float4*)&g_theta[b*8];
    float2 t45 = *(const float2*)&g_theta[b*8+4];
    float gx = (float)w*(2.f/255.f) - 1.f;
    float gy = (float)h*(2.f/255.f) - 1.f;
    float tx = gx*t03.x + gy*t03.w + t03.z;
    float ty = gx*t03.y + gy*t45.x + t45.y;
    float xf = 0.5f*((tx+1.f)*255.f);
    float yf = 0.5f*((ty+1.f)*255.f);
    float x0f = floorf(xf), y0f = floorf(yf);
    float x0c = fminf(fmaxf(x0f,0.f),255.f);
    float x1c = fminf(fmaxf(x0f+1.f,0.f),255.f);
    float y0c = fminf(fmaxf(y0f,0.f),255.f);
    float y1c = fminf(fmaxf(y0f+1.f,0.f),255.f);
    float wa=(x1c-xf)*(y1c-yf), wb=(x1c-xf)*(yf-y0c);
    float wc=(xf-x0c)*(y1c-yf), wd=(xf-x0c)*(yf-y0c);
    int xi0=(int)x0c, xi1=(int)x1c, yi0=(int)y0c, yi1=(int)y1c;

    // x_int (nearest-upsampled, padded 32ch) bilinear with tap dedup
    const float* xb = &g_xintp[b*32768];
    int ca = ((yi0>>3)*32 + (xi0>>3))*32;
    int cb = ((yi1>>3)*32 + (xi0>>3))*32;
    int cc = ((yi0>>3)*32 + (xi1>>3))*32;
    int cd = ((yi1>>3)*32 + (xi1>>3))*32;
    float4 Ia = *(const float4*)&xb[ca + q*4];
    float4 Ib = (cb==ca) ? Ia : *(const float4*)&xb[cb + q*4];
    float4 Ic = (cc==ca) ? Ia : *(const float4*)&xb[cc + q*4];
    float4 Id;
    if (cd==cb)      Id = Ib;
    else if (cd==cc) Id = Ic;
    else             Id = *(const float4*)&xb[cd + q*4];

    float4 val;
    val.x = wa*Ia.x + wb*Ib.x + wc*Ic.x + wd*Id.x;
    val.y = wa*Ia.y + wb*Ib.y + wc*Ic.y + wd*Id.y;
    val.z = wa*Ia.z + wb*Ib.z + wc*Ic.z + wd*Id.z;
    val.w = wa*Ia.w + wb*Ib.w + wc*Ic.w + wd*Id.w;

    if (q==0){
        const float* xb0 = x + b*65536;
        val.x = wa*xb0[yi0*256+xi0] + wb*xb0[yi1*256+xi0]
              + wc*xb0[yi0*256+xi1] + wd*xb0[yi1*256+xi1];
    }
    val.x = (val.x>=0.f)? val.x : 0.1f*val.x;
    val.y = (val.y>=0.f)? val.y : 0.1f*val.y;
    val.z = (val.z>=0.f)? val.z : 0.1f*val.z;
    val.w = (val.w>=0.f)? val.w : 0.1f*val.w;
    *(float4*)&out[pix*32 + q*4] = val;
}

extern "C" void kernel_launch(void* const* d_in, const int* in_sizes, int n_in,
                              void* d_out, int out_size)
{
    const float* x   = (const float*)d_in[0];
    const float* c1k = (const float*)d_in[1];
    const float* c1b = (const float*)d_in[2];
    const float* c2k = (const float*)d_in[3];
    const float* c2b = (const float*)d_in[4];
    const float* c3k = (const float*)d_in[5];
    const float* c3b = (const float*)d_in[6];
    const float* bng = (const float*)d_in[7];
    const float* bnb = (const float*)d_in[8];
    const float* bnm = (const float*)d_in[9];
    const float* bnv = (const float*)d_in[10];
    const float* d1k = (const float*)d_in[11];
    const float* d1b = (const float*)d_in[12];
    const float* d2k = (const float*)d_in[13];
    const float* d2b = (const float*)d_in[14];
    const float* d3k = (const float*)d_in[15];
    const float* d3b = (const float*)d_in[16];
    float* out = (float*)d_out;

    dim3 t16(16,16);
    conv1pool_k<<<dim3(8,8,16), t16>>>(x, c1k, c1b);
    conv2pool_k<<<dim3(4,4,16), t16>>>(c2k, c2b);
    conv3pool_k<<<dim3(4,4,16), 256>>>(c3k, c3b);
    dense1_k<<<62,256>>>(bng, bnb, bnm, bnv, d1k);
    denserest_k<<<16,96>>>(d1b, d2k, d2b, d3k, d3b);
    sampler_k<<<16*256*256/32, 256>>>(x, out);
}

// round 3
// speedup vs baseline: 2.0232x; 1.3439x over previous
#include <cuda_runtime.h>

#define FEAT (32*32*31)   // 31744
#define BN_EPS 1e-3f
#define D1_BLKS 248        // 31744 / 128

__device__ __align__(16) float g_buf1[16*128*128*8];   // conv1+pool out
__device__ __align__(16) float g_buf2[16*64*64*16];    // conv2+pool out
__device__ __align__(16) float g_xintp[16*32*32*32];   // conv3+pool out, padded: slot 1+c
__device__ __align__(16) float g_f1p[D1_BLKS*16*64];   // dense1 partials
__device__ __align__(16) float g_theta[16*8];          // theta padded to 8/b

// ---- f32x2 helpers ----
#define FFMA2(d,a,b,c) asm("fma.rn.f32x2 %0,%1,%2,%3;" : "=l"(d) : "l"(a), "l"(b), "l"(c))
#define PK2(d,lo,hi)   asm("mov.b64 %0,{%1,%2};" : "=l"(d) : "r"(__float_as_uint(lo)), "r"(__float_as_uint(hi)))
#define UNPK2(lo,hi,v) do { unsigned _l,_h; asm("mov.b64 {%0,%1},%2;" : "=r"(_l), "=r"(_h) : "l"(v)); lo=__uint_as_float(_l); hi=__uint_as_float(_h); } while(0)

// ---------------- conv1 (1->8) + relu + maxpool2 ----------------
__global__ void conv1pool_k(const float* __restrict__ x,
                            const float* __restrict__ k,
                            const float* __restrict__ bias)
{
    __shared__ float sp[34*36];
    __shared__ float sk[72];
    __shared__ float sb[8];
    int b = blockIdx.z;
    int px0 = blockIdx.x*16, py0 = blockIdx.y*16;
    int tid = threadIdx.y*16+threadIdx.x;
    int iy0 = py0*2-1, ix0 = px0*2-1;
    for (int idx = tid; idx < 34*34; idx += 256) {
        int yy = idx/34, xx = idx-yy*34;
        int gy = iy0+yy, gx = ix0+xx;
        float v = 0.f;
        if ((unsigned)gy < 256u && (unsigned)gx < 256u) v = x[(b*256+gy)*256+gx];
        sp[yy*36+xx] = v;
    }
    if (tid < 72) sk[tid] = k[tid];
    if (tid < 8)  sb[tid] = bias[tid];
    __syncthreads();
    int tx = threadIdx.x, ty = threadIdx.y;
    float p[4][4];
    #pragma unroll
    for (int r=0;r<4;r++)
      #pragma unroll
      for (int c=0;c<4;c++)
        p[r][c] = sp[(ty*2+r)*36 + tx*2+c];
    float o[8];
    #pragma unroll
    for (int co=0;co<8;co++){
        float w[9];
        #pragma unroll
        for (int t=0;t<9;t++) w[t]=sk[t*8+co];
        float s00=0.f,s01=0.f,s10=0.f,s11=0.f;
        #pragma unroll
        for (int r=0;r<3;r++)
          #pragma unroll
          for (int c=0;c<3;c++){
            float wv = w[r*3+c];
            s00 += p[r][c]*wv;
            s01 += p[r][c+1]*wv;
            s10 += p[r+1][c]*wv;
            s11 += p[r+1][c+1]*wv;
          }
        float m = fmaxf(fmaxf(s00,s01),fmaxf(s10,s11)) + sb[co];
        o[co] = fmaxf(m, 0.f);
    }
    int py = py0+ty, px = px0+tx;
    float4* outp = (float4*)&g_buf1[((b*128+py)*128+px)*8];
    outp[0] = make_float4(o[0],o[1],o[2],o[3]);
    outp[1] = make_float4(o[4],o[5],o[6],o[7]);
}

// ---------------- conv2 (8->16) + relu + maxpool2 (f32x2) ----------------
__global__ void __launch_bounds__(256) conv2pool_k(const float* __restrict__ k,
                                                   const float* __restrict__ bias)
{
    __shared__ float sp[8][34*36];
    __shared__ __align__(8) float sw[1152];
    __shared__ float sb[16];
    int b = blockIdx.z;
    int px0 = blockIdx.x*16, py0 = blockIdx.y*16;
    int tid = threadIdx.y*16+threadIdx.x;
    int iy0 = py0*2-1, ix0 = px0*2-1;
    for (int idx=tid; idx<34*34*2; idx+=256){
        int q = idx & 1; int pix = idx >> 1;
        int yy = pix/34, xx = pix - yy*34;
        int gy = iy0+yy, gx = ix0+xx;
        float4 v = make_float4(0.f,0.f,0.f,0.f);
        if ((unsigned)gy<128u && (unsigned)gx<128u)
            v = *(const float4*)&g_buf1[((b*128+gy)*128+gx)*8 + q*4];
        int off = yy*36+xx;
        sp[q*4+0][off]=v.x; sp[q*4+1][off]=v.y; sp[q*4+2][off]=v.z; sp[q*4+3][off]=v.w;
    }
    for (int idx=tid; idx<1152; idx+=256) sw[idx]=k[idx];
    if (tid<16) sb[tid]=bias[tid];
    __syncthreads();
    int tx=threadIdx.x, ty=threadIdx.y;
    unsigned long long acc2[4][8];
    #pragma unroll
    for (int p_=0;p_<4;p_++)
      #pragma unroll
      for(int kk=0;kk<8;kk++) acc2[p_][kk]=0ull;

    #pragma unroll 1
    for (int t=0;t<9;t++){
        int dy=t/3, dx=t-3*dy;
        #pragma unroll 1
        for (int ci=0;ci<8;ci++){
            const unsigned long long* wp = (const unsigned long long*)&sw[(t*8+ci)*16];
            unsigned long long w2[8];
            #pragma unroll
            for (int kk=0;kk<8;kk++) w2[kk]=wp[kk];
            const float* pl = sp[ci];
            int base = (ty*2+dy)*36 + tx*2+dx;
            float v00 = pl[base];
            float v01 = pl[base+1];
            float v10 = pl[base+36];
            float v11 = pl[base+37];
            unsigned long long p00,p01,p10,p11;
            PK2(p00,v00,v00); PK2(p01,v01,v01); PK2(p10,v10,v10); PK2(p11,v11,v11);
            #pragma unroll
            for (int kk=0;kk<8;kk++){
                FFMA2(acc2[0][kk], p00, w2[kk], acc2[0][kk]);
                FFMA2(acc2[1][kk], p01, w2[kk], acc2[1][kk]);
                FFMA2(acc2[2][kk], p10, w2[kk], acc2[2][kk]);
                FFMA2(acc2[3][kk], p11, w2[kk], acc2[3][kk]);
            }
        }
    }
    int py=py0+ty, px=px0+tx;
    float* outp = &g_buf2[((b*64+py)*64+px)*16];
    #pragma unroll
    for (int kk=0;kk<8;kk++){
        float a0,a1,b0,b1,c0,c1,d0,d1;
        UNPK2(a0,a1,acc2[0][kk]); UNPK2(b0,b1,acc2[1][kk]);
        UNPK2(c0,c1,acc2[2][kk]); UNPK2(d0,d1,acc2[3][kk]);
        float m0 = fmaxf(fmaxf(a0,b0),fmaxf(c0,d0))+sb[kk*2+0];
        float m1 = fmaxf(fmaxf(a1,b1),fmaxf(c1,d1))+sb[kk*2+1];
        outp[kk*2+0] = fmaxf(m0,0.f);
        outp[kk*2+1] = fmaxf(m1,0.f);
    }
}

// ---------------- conv3 (16->31) + relu + maxpool2 (f32x2, padded out) ----------------
__global__ void __launch_bounds__(256) conv3pool_k(const float* __restrict__ k,
                                                   const float* __restrict__ bias)
{
    __shared__ float sp[16][18*20];
    __shared__ __align__(8) float sw[9*16*32];   // co padded to 32
    __shared__ float sb[32];
    int b = blockIdx.z;
    int px0 = blockIdx.x*8, py0 = blockIdx.y*8;
    int tid = threadIdx.x;
    int iy0 = py0*2-1, ix0 = px0*2-1;
    for (int idx=tid; idx<18*18*4; idx+=256){
        int q = idx & 3; int pix = idx >> 2;
        int yy=pix/18, xx=pix-yy*18;
        int gy=iy0+yy, gx=ix0+xx;
        float4 v=make_float4(0.f,0.f,0.f,0.f);
        if ((unsigned)gy<64u && (unsigned)gx<64u)
            v = *(const float4*)&g_buf2[((b*64+gy)*64+gx)*16 + q*4];
        int off=yy*20+xx;
        sp[q*4+0][off]=v.x; sp[q*4+1][off]=v.y; sp[q*4+2][off]=v.z; sp[q*4+3][off]=v.w;
    }
    for (int idx=tid; idx<9*16*32; idx+=256){
        int co = idx & 31; int tc = idx >> 5;
        sw[idx] = (co<31) ? k[tc*31+co] : 0.f;
    }
    if (tid<32) sb[tid] = (tid<31)? bias[tid] : 0.f;
    __syncthreads();
    int g = tid>>6; int pid = tid&63; int tx=pid&7, ty=pid>>3;
    int cobase = g*8;
    unsigned long long acc2[4][4];
    #pragma unroll
    for (int p_=0;p_<4;p_++)
      #pragma unroll
      for (int kk=0;kk<4;kk++) acc2[p_][kk]=0ull;

    #pragma unroll 1
    for (int t=0;t<9;t++){
        int dy=t/3, dx=t-3*dy;
        #pragma unroll 1
        for (int ci=0;ci<16;ci++){
            const unsigned long long* wp = (const unsigned long long*)&sw[(t*16+ci)*32+cobase];
            unsigned long long w2[4];
            #pragma unroll
            for (int kk=0;kk<4;kk++) w2[kk]=wp[kk];
            const float* pl = sp[ci];
            int base=(ty*2+dy)*20+tx*2+dx;
            float v00=pl[base], v01=pl[base+1], v10=pl[base+20], v11=pl[base+21];
            unsigned long long p00,p01,p10,p11;
            PK2(p00,v00,v00); PK2(p01,v01,v01); PK2(p10,v10,v10); PK2(p11,v11,v11);
            #pragma unroll
            for (int kk=0;kk<4;kk++){
                FFMA2(acc2[0][kk], p00, w2[kk], acc2[0][kk]);
                FFMA2(acc2[1][kk], p01, w2[kk], acc2[1][kk]);
                FFMA2(acc2[2][kk], p10, w2[kk], acc2[2][kk]);
                FFMA2(acc2[3][kk], p11, w2[kk], acc2[3][kk]);
            }
        }
    }
    int py=py0+ty, px=px0+tx;
    float* outp = &g_xintp[((b*32+py)*32+px)*32];   // padded: slot 1+co
    #pragma unroll
    for (int kk=0;kk<4;kk++){
        float a0,a1,b0,b1,c0,c1,d0,d1;
        UNPK2(a0,a1,acc2[0][kk]); UNPK2(b0,b1,acc2[1][kk]);
        UNPK2(c0,c1,acc2[2][kk]); UNPK2(d0,d1,acc2[3][kk]);
        int co0 = cobase+kk*2, co1 = cobase+kk*2+1;
        float m0 = fmaxf(fmaxf(a0,b0),fmaxf(c0,d0))+sb[co0];
        float m1 = fmaxf(fmaxf(a1,b1),fmaxf(c1,d1))+sb[co1];
        if (co0<31) outp[1+co0] = fmaxf(m0,0.f);
        if (co1<31) outp[1+co1] = fmaxf(m1,0.f);
    }
}

// ---------------- dense1: BN + (16x31744)@(31744x64), staged split-K ----------------
// 248 blocks, each handles 128 K-rows. Weights streamed to smem via float4
// (high MLP, DRAM-bound), then compute entirely from smem.
__global__ void __launch_bounds__(256) dense1_k(const float* __restrict__ gamma,
                                                const float* __restrict__ beta,
                                                const float* __restrict__ mean,
                                                const float* __restrict__ var,
                                                const float* __restrict__ Wd)
{
    __shared__ float fsm[128*17];    // fsm[il*17 + b]
    __shared__ __align__(16) float wsm[128*64];
    int i0 = blockIdx.x*128;
    int tid = threadIdx.x;
    // stage weights: 8192 floats = 2048 float4, 8 per thread, independent
    {
        const float4* wsrc = (const float4*)&Wd[i0*64];
        float4* wdst = (float4*)wsm;
        #pragma unroll
        for (int r=0;r<8;r++)
            wdst[tid + r*256] = wsrc[tid + r*256];
    }
    // stage BN'd features: 128 il x 16 b
    for (int idx=tid; idx<128*16; idx+=256){
        int bb = idx>>7; int il = idx & 127;
        int i = i0+il;
        int cell = i/31; int c = i - cell*31;
        float xv = g_xintp[bb*32768 + cell*32 + 1 + c];
        float fv = (xv - mean[i]) * rsqrtf(var[i]+BN_EPS) * gamma[i] + beta[i];
        fsm[il*17+bb] = fv;
    }
    __syncthreads();
    int j = tid & 63, bg = tid>>6;
    float a0=0.f,a1=0.f,a2=0.f,a3=0.f;
    #pragma unroll 8
    for (int il=0; il<128; il++){
        float w = wsm[il*64 + j];
        const float* f = &fsm[il*17 + bg*4];
        a0 += f[0]*w; a1 += f[1]*w; a2 += f[2]*w; a3 += f[3]*w;
    }
    float* o = &g_f1p[blockIdx.x*1024];
    o[(bg*4+0)*64+j] = a0;
    o[(bg*4+1)*64+j] = a1;
    o[(bg*4+2)*64+j] = a2;
    o[(bg*4+3)*64+j] = a3;
}

// ---------------- reduce partials + dense2 + dense3 -> theta ----------------
__global__ void denserest_k(const float* __restrict__ d1b,
                            const float* __restrict__ d2k, const float* __restrict__ d2b,
                            const float* __restrict__ d3k, const float* __restrict__ d3b)
{
    __shared__ float h1[64], h2[96];
    int b=blockIdx.x, t=threadIdx.x;  // 96 threads
    if (t<64){
        float s = 0.f;
        #pragma unroll 8
        for (int p=0;p<D1_BLKS;p++) s += g_f1p[p*1024 + b*64 + t];
        h1[t] = fmaxf(s + d1b[t], 0.f);
    }
    __syncthreads();
    float s = d2b[t];
    for (int i=0;i<64;i++) s += h1[i]*d2k[i*96+t];
    h2[t] = fmaxf(s,0.f);
    __syncthreads();
    if (t<6){
        float s2 = d3b[t];
        for (int i=0;i<96;i++) s2 += h2[i]*d3k[i*6+t];
        g_theta[b*8+t] = s2;
    }
}

// ---------------- grid + resize + concat + bilinear + leaky (vectorized) ----------------
// thread = (pixel, channel-quad q in 0..7); block = 32 pixels
__global__ void __launch_bounds__(256) sampler_k(const float* __restrict__ x,
                                                 float* __restrict__ out)
{
    int tid = threadIdx.x;
    int pix = blockIdx.x*32 + (tid>>3);
    int q = tid & 7;
    int b = pix >> 16;
    int h = (pix >> 8) & 255;
    int w = pix & 255;
    float4 t03 = *(const float4*)&g_theta[b*8];
    float2 t45 = *(const float2*)&g_theta[b*8+4];
    float gx = (float)w*(2.f/255.f) - 1.f;
    float gy = (float)h*(2.f/255.f) - 1.f;
    float tx = gx*t03.x + gy*t03.w + t03.z;
    float ty = gx*t03.y + gy*t45.x + t45.y;
    float xf = 0.5f*((tx+1.f)*255.f);
    float yf = 0.5f*((ty+1.f)*255.f);
    float x0f = floorf(xf), y0f = floorf(yf);
    float x0c = fminf(fmaxf(x0f,0.f),255.f);
    float x1c = fminf(fmaxf(x0f+1.f,0.f),255.f);
    float y0c = fminf(fmaxf(y0f,0.f),255.f);
    float y1c = fminf(fmaxf(y0f+1.f,0.f),255.f);
    float wa=(x1c-xf)*(y1c-yf), wb=(x1c-xf)*(yf-y0c);
    float wc=(xf-x0c)*(y1c-yf), wd=(xf-x0c)*(yf-y0c);
    int xi0=(int)x0c, xi1=(int)x1c, yi0=(int)y0c, yi1=(int)y1c;

    // x_int (nearest-upsampled, padded 32ch) bilinear with tap dedup
    const float* xb = &g_xintp[b*32768];
    int ca = ((yi0>>3)*32 + (xi0>>3))*32;
    int cb = ((yi1>>3)*32 + (xi0>>3))*32;
    int cc = ((yi0>>3)*32 + (xi1>>3))*32;
    int cd = ((yi1>>3)*32 + (xi1>>3))*32;
    float4 Ia = *(const float4*)&xb[ca + q*4];
    float4 Ib = (cb==ca) ? Ia : *(const float4*)&xb[cb + q*4];
    float4 Ic = (cc==ca) ? Ia : *(const float4*)&xb[cc + q*4];
    float4 Id;
    if (cd==cb)      Id = Ib;
    else if (cd==cc) Id = Ic;
    else             Id = *(const float4*)&xb[cd + q*4];

    float4 val;
    val.x = wa*Ia.x + wb*Ib.x + wc*Ic.x + wd*Id.x;
    val.y = wa*Ia.y + wb*Ib.y + wc*Ic.y + wd*Id.y;
    val.z = wa*Ia.z + wb*Ib.z + wc*Ic.z + wd*Id.z;
    val.w = wa*Ia.w + wb*Ib.w + wc*Ic.w + wd*Id.w;

    if (q==0){
        const float* xb0 = x + b*65536;
        val.x = wa*xb0[yi0*256+xi0] + wb*xb0[yi1*256+xi0]
              + wc*xb0[yi0*256+xi1] + wd*xb0[yi1*256+xi1];
    }
    val.x = (val.x>=0.f)? val.x : 0.1f*val.x;
    val.y = (val.y>=0.f)? val.y : 0.1f*val.y;
    val.z = (val.z>=0.f)? val.z : 0.1f*val.z;
    val.w = (val.w>=0.f)? val.w : 0.1f*val.w;
    *(float4*)&out[pix*32 + q*4] = val;
}

extern "C" void kernel_launch(void* const* d_in, const int* in_sizes, int n_in,
                              void* d_out, int out_size)
{
    const float* x   = (const float*)d_in[0];
    const float* c1k = (const float*)d_in[1];
    const float* c1b = (const float*)d_in[2];
    const float* c2k = (const float*)d_in[3];
    const float* c2b = (const float*)d_in[4];
    const float* c3k = (const float*)d_in[5];
    const float* c3b = (const float*)d_in[6];
    const float* bng = (const float*)d_in[7];
    const float* bnb = (const float*)d_in[8];
    const float* bnm = (const float*)d_in[9];
    const float* bnv = (const float*)d_in[10];
    const float* d1k = (const float*)d_in[11];
    const float* d1b = (const float*)d_in[12];
    const float* d2k = (const float*)d_in[13];
    const float* d2b = (const float*)d_in[14];
    const float* d3k = (const float*)d_in[15];
    const float* d3b = (const float*)d_in[16];
    float* out = (float*)d_out;

    dim3 t16(16,16);
    conv1pool_k<<<dim3(8,8,16), t16>>>(x, c1k, c1b);
    conv2pool_k<<<dim3(4,4,16), t16>>>(c2k, c2b);
    conv3pool_k<<<dim3(4,4,16), 256>>>(c3k, c3b);
    dense1_k<<<D1_BLKS,256>>>(bng, bnb, bnm, bnv, d1k);
    denserest_k<<<16,96>>>(d1b, d2k, d2b, d3k, d3b);
    sampler_k<<<16*256*256/32, 256>>>(x, out);
}

// round 5
// speedup vs baseline: 2.2183x; 1.0964x over previous
#include <cuda_runtime.h>

#define FEAT (32*32*31)   // 31744
#define BN_EPS 1e-3f
#define D1_BLKS 496        // 31744 / 64

__device__ __align__(16) float g_buf1[16*128*128*8];   // conv1+pool out
__device__ __align__(16) float g_buf2[16*64*64*16];    // conv2+pool out
__device__ __align__(16) float g_xintp[16*32*32*32];   // conv3+pool out, padded: slot 1+c
__device__ __align__(16) float g_f1p[D1_BLKS*16*64];   // dense1 partials
__device__ __align__(16) float g_theta[16*8];          // theta padded to 8/b

// ---- f32x2 helpers ----
#define FFMA2(d,a,b,c) asm("fma.rn.f32x2 %0,%1,%2,%3;" : "=l"(d) : "l"(a), "l"(b), "l"(c))
#define PK2(d,lo,hi)   asm("mov.b64 %0,{%1,%2};" : "=l"(d) : "r"(__float_as_uint(lo)), "r"(__float_as_uint(hi)))
#define UNPK2(lo,hi,v) do { unsigned _l,_h; asm("mov.b64 {%0,%1},%2;" : "=r"(_l), "=r"(_h) : "l"(v)); lo=__uint_as_float(_l); hi=__uint_as_float(_h); } while(0)

// ---------------- conv1 (1->8) + relu + maxpool2 (split by batch for profiling) ----------------
__global__ void conv1pool_k(const float* __restrict__ x,
                            const float* __restrict__ k,
                            const float* __restrict__ bias,
                            int b0)
{
    __shared__ float sp[34*36];
    __shared__ float sk[72];
    __shared__ float sb[8];
    int b = blockIdx.z + b0;
    int px0 = blockIdx.x*16, py0 = blockIdx.y*16;
    int tid = threadIdx.y*16+threadIdx.x;
    int iy0 = py0*2-1, ix0 = px0*2-1;
    for (int idx = tid; idx < 34*34; idx += 256) {
        int yy = idx/34, xx = idx-yy*34;
        int gy = iy0+yy, gx = ix0+xx;
        float v = 0.f;
        if ((unsigned)gy < 256u && (unsigned)gx < 256u) v = x[(b*256+gy)*256+gx];
        sp[yy*36+xx] = v;
    }
    if (tid < 72) sk[tid] = k[tid];
    if (tid < 8)  sb[tid] = bias[tid];
    __syncthreads();
    int tx = threadIdx.x, ty = threadIdx.y;
    float p[4][4];
    #pragma unroll
    for (int r=0;r<4;r++)
      #pragma unroll
      for (int c=0;c<4;c++)
        p[r][c] = sp[(ty*2+r)*36 + tx*2+c];
    float o[8];
    #pragma unroll
    for (int co=0;co<8;co++){
        float w[9];
        #pragma unroll
        for (int t=0;t<9;t++) w[t]=sk[t*8+co];
        float s00=0.f,s01=0.f,s10=0.f,s11=0.f;
        #pragma unroll
        for (int r=0;r<3;r++)
          #pragma unroll
          for (int c=0;c<3;c++){
            float wv = w[r*3+c];
            s00 += p[r][c]*wv;
            s01 += p[r][c+1]*wv;
            s10 += p[r+1][c]*wv;
            s11 += p[r+1][c+1]*wv;
          }
        float m = fmaxf(fmaxf(s00,s01),fmaxf(s10,s11)) + sb[co];
        o[co] = fmaxf(m, 0.f);
    }
    int py = py0+ty, px = px0+tx;
    float4* outp = (float4*)&g_buf1[((b*128+py)*128+px)*8];
    outp[0] = make_float4(o[0],o[1],o[2],o[3]);
    outp[1] = make_float4(o[4],o[5],o[6],o[7]);
}

// ---------------- conv2 (8->16) + relu + maxpool2 (f32x2) ----------------
__global__ void __launch_bounds__(256) conv2pool_k(const float* __restrict__ k,
                                                   const float* __restrict__ bias)
{
    __shared__ float sp[8][34*36];
    __shared__ __align__(8) float sw[1152];
    __shared__ float sb[16];
    int b = blockIdx.z;
    int px0 = blockIdx.x*16, py0 = blockIdx.y*16;
    int tid = threadIdx.y*16+threadIdx.x;
    int iy0 = py0*2-1, ix0 = px0*2-1;
    for (int idx=tid; idx<34*34*2; idx+=256){
        int q = idx & 1; int pix = idx >> 1;
        int yy = pix/34, xx = pix - yy*34;
        int gy = iy0+yy, gx = ix0+xx;
        float4 v = make_float4(0.f,0.f,0.f,0.f);
        if ((unsigned)gy<128u && (unsigned)gx<128u)
            v = *(const float4*)&g_buf1[((b*128+gy)*128+gx)*8 + q*4];
        int off = yy*36+xx;
        sp[q*4+0][off]=v.x; sp[q*4+1][off]=v.y; sp[q*4+2][off]=v.z; sp[q*4+3][off]=v.w;
    }
    for (int idx=tid; idx<1152; idx+=256) sw[idx]=k[idx];
    if (tid<16) sb[tid]=bias[tid];
    __syncthreads();
    int tx=threadIdx.x, ty=threadIdx.y;
    unsigned long long acc2[4][8];
    #pragma unroll
    for (int p_=0;p_<4;p_++)
      #pragma unroll
      for(int kk=0;kk<8;kk++) acc2[p_][kk]=0ull;

    #pragma unroll 1
    for (int t=0;t<9;t++){
        int dy=t/3, dx=t-3*dy;
        #pragma unroll 2
        for (int ci=0;ci<8;ci++){
            const unsigned long long* wp = (const unsigned long long*)&sw[(t*8+ci)*16];
            unsigned long long w2[8];
            #pragma unroll
            for (int kk=0;kk<8;kk++) w2[kk]=wp[kk];
            const float* pl = sp[ci];
            int base = (ty*2+dy)*36 + tx*2+dx;
            float v00 = pl[base];
            float v01 = pl[base+1];
            float v10 = pl[base+36];
            float v11 = pl[base+37];
            unsigned long long p00,p01,p10,p11;
            PK2(p00,v00,v00); PK2(p01,v01,v01); PK2(p10,v10,v10); PK2(p11,v11,v11);
            #pragma unroll
            for (int kk=0;kk<8;kk++){
                FFMA2(acc2[0][kk], p00, w2[kk], acc2[0][kk]);
                FFMA2(acc2[1][kk], p01, w2[kk], acc2[1][kk]);
                FFMA2(acc2[2][kk], p10, w2[kk], acc2[2][kk]);
                FFMA2(acc2[3][kk], p11, w2[kk], acc2[3][kk]);
            }
        }
    }
    int py=py0+ty, px=px0+tx;
    float* outp = &g_buf2[((b*64+py)*64+px)*16];
    #pragma unroll
    for (int kk=0;kk<8;kk++){
        float a0,a1,b0,b1,c0,c1,d0,d1;
        UNPK2(a0,a1,acc2[0][kk]); UNPK2(b0,b1,acc2[1][kk]);
        UNPK2(c0,c1,acc2[2][kk]); UNPK2(d0,d1,acc2[3][kk]);
        float m0 = fmaxf(fmaxf(a0,b0),fmaxf(c0,d0))+sb[kk*2+0];
        float m1 = fmaxf(fmaxf(a1,b1),fmaxf(c1,d1))+sb[kk*2+1];
        outp[kk*2+0] = fmaxf(m0,0.f);
        outp[kk*2+1] = fmaxf(m1,0.f);
    }
}

// ---------------- conv3 (16->31) + relu + maxpool2 (f32x2, padded out) ----------------
__global__ void __launch_bounds__(256) conv3pool_k(const float* __restrict__ k,
                                                   const float* __restrict__ bias)
{
    __shared__ float sp[16][18*20];
    __shared__ __align__(8) float sw[9*16*32];   // co padded to 32
    __shared__ float sb[32];
    int b = blockIdx.z;
    int px0 = blockIdx.x*8, py0 = blockIdx.y*8;
    int tid = threadIdx.x;
    int iy0 = py0*2-1, ix0 = px0*2-1;
    for (int idx=tid; idx<18*18*4; idx+=256){
        int q = idx & 3; int pix = idx >> 2;
        int yy=pix/18, xx=pix-yy*18;
        int gy=iy0+yy, gx=ix0+xx;
        float4 v=make_float4(0.f,0.f,0.f,0.f);
        if ((unsigned)gy<64u && (unsigned)gx<64u)
            v = *(const float4*)&g_buf2[((b*64+gy)*64+gx)*16 + q*4];
        int off=yy*20+xx;
        sp[q*4+0][off]=v.x; sp[q*4+1][off]=v.y; sp[q*4+2][off]=v.z; sp[q*4+3][off]=v.w;
    }
    for (int idx=tid; idx<9*16*32; idx+=256){
        int co = idx & 31; int tc = idx >> 5;
        sw[idx] = (co<31) ? k[tc*31+co] : 0.f;
    }
    if (tid<32) sb[tid] = (tid<31)? bias[tid] : 0.f;
    __syncthreads();
    int g = tid>>6; int pid = tid&63; int tx=pid&7, ty=pid>>3;
    int cobase = g*8;
    unsigned long long acc2[4][4];
    #pragma unroll
    for (int p_=0;p_<4;p_++)
      #pragma unroll
      for (int kk=0;kk<4;kk++) acc2[p_][kk]=0ull;

    #pragma unroll 1
    for (int t=0;t<9;t++){
        int dy=t/3, dx=t-3*dy;
        #pragma unroll 4
        for (int ci=0;ci<16;ci++){
            const unsigned long long* wp = (const unsigned long long*)&sw[(t*16+ci)*32+cobase];
            unsigned long long w2[4];
            #pragma unroll
            for (int kk=0;kk<4;kk++) w2[kk]=wp[kk];
            const float* pl = sp[ci];
            int base=(ty*2+dy)*20+tx*2+dx;
            float v00=pl[base], v01=pl[base+1], v10=pl[base+20], v11=pl[base+21];
            unsigned long long p00,p01,p10,p11;
            PK2(p00,v00,v00); PK2(p01,v01,v01); PK2(p10,v10,v10); PK2(p11,v11,v11);
            #pragma unroll
            for (int kk=0;kk<4;kk++){
                FFMA2(acc2[0][kk], p00, w2[kk], acc2[0][kk]);
                FFMA2(acc2[1][kk], p01, w2[kk], acc2[1][kk]);
                FFMA2(acc2[2][kk], p10, w2[kk], acc2[2][kk]);
                FFMA2(acc2[3][kk], p11, w2[kk], acc2[3][kk]);
            }
        }
    }
    int py=py0+ty, px=px0+tx;
    float* outp = &g_xintp[((b*32+py)*32+px)*32];   // padded: slot 1+co
    #pragma unroll
    for (int kk=0;kk<4;kk++){
        float a0,a1,b0,b1,c0,c1,d0,d1;
        UNPK2(a0,a1,acc2[0][kk]); UNPK2(b0,b1,acc2[1][kk]);
        UNPK2(c0,c1,acc2[2][kk]); UNPK2(d0,d1,acc2[3][kk]);
        int co0 = cobase+kk*2, co1 = cobase+kk*2+1;
        float m0 = fmaxf(fmaxf(a0,b0),fmaxf(c0,d0))+sb[co0];
        float m1 = fmaxf(fmaxf(a1,b1),fmaxf(c1,d1))+sb[co1];
        if (co0<31) outp[1+co0] = fmaxf(m0,0.f);
        if (co1<31) outp[1+co1] = fmaxf(m1,0.f);
    }
}

// ---------------- dense1: BN + (16x31744)@(31744x64), staged split-K ----------------
// 496 blocks x 64 K-rows. Weights via float4 stage; fsm stride-16 -> LDS.128.
__global__ void __launch_bounds__(256) dense1_k(const float* __restrict__ gamma,
                                                const float* __restrict__ beta,
                                                const float* __restrict__ mean,
                                                const float* __restrict__ var,
                                                const float* __restrict__ Wd)
{
    __shared__ __align__(16) float fsm[64*16];
    __shared__ __align__(16) float wsm[64*64];
    int i0 = blockIdx.x*64;
    int tid = threadIdx.x;
    {
        const float4* wsrc = (const float4*)&Wd[i0*64];
        float4* wdst = (float4*)wsm;
        #pragma unroll
        for (int r=0;r<4;r++)
            wdst[tid + r*256] = wsrc[tid + r*256];
    }
    #pragma unroll
    for (int r=0;r<4;r++){
        int idx = tid + r*256;
        int il = idx>>4; int bb = idx & 15;
        int i = i0+il;
        int cell = i/31; int c = i - cell*31;
        float xv = g_xintp[bb*32768 + cell*32 + 1 + c];
        fsm[il*16+bb] = (xv - mean[i]) * rsqrtf(var[i]+BN_EPS) * gamma[i] + beta[i];
    }
    __syncthreads();
    int j = tid & 63, bg = tid>>6;
    float a0=0.f,a1=0.f,a2=0.f,a3=0.f;
    #pragma unroll 8
    for (int il=0; il<64; il++){
        float w = wsm[il*64 + j];
        float4 f = *(const float4*)&fsm[il*16 + bg*4];
        a0 += f.x*w; a1 += f.y*w; a2 += f.z*w; a3 += f.w*w;
    }
    float* o = &g_f1p[blockIdx.x*1024];
    o[(bg*4+0)*64+j] = a0;
    o[(bg*4+1)*64+j] = a1;
    o[(bg*4+2)*64+j] = a2;
    o[(bg*4+3)*64+j] = a3;
}

// ---------------- reduce partials + dense2 + dense3 -> theta ----------------
__global__ void __launch_bounds__(256) denserest_k(const float* __restrict__ d1b,
                            const float* __restrict__ d2k, const float* __restrict__ d2b,
                            const float* __restrict__ d3k, const float* __restrict__ d3b)
{
    __shared__ float red[4][64];
    __shared__ float h1[64], h2[96];
    int b=blockIdx.x, t=threadIdx.x;  // 256 threads
    int j = t & 63, g = t>>6;
    float s = 0.f;
    #pragma unroll 4
    for (int p=g; p<D1_BLKS; p+=4) s += g_f1p[p*1024 + b*64 + j];
    red[g][j] = s;
    __syncthreads();
    if (t<64)
        h1[t] = fmaxf(red[0][t]+red[1][t]+red[2][t]+red[3][t] + d1b[t], 0.f);
    __syncthreads();
    if (t<96){
        float s2 = d2b[t];
        for (int i=0;i<64;i++) s2 += h1[i]*d2k[i*96+t];
        h2[t] = fmaxf(s2,0.f);
    }
    __syncthreads();
    if (t<6){
        float s3 = d3b[t];
        for (int i=0;i<96;i++) s3 += h2[i]*d3k[i*6+t];
        g_theta[b*8+t] = s3;
    }
}

// ---------------- grid + resize + concat + bilinear + leaky (vectorized) ----------------
__global__ void __launch_bounds__(256) sampler_k(const float* __restrict__ x,
                                                 float* __restrict__ out)
{
    int tid = threadIdx.x;
    int pix = blockIdx.x*32 + (tid>>3);
    int q = tid & 7;
    int b = pix >> 16;
    int h = (pix >> 8) & 255;
    int w = pix & 255;
    float4 t03 = *(const float4*)&g_theta[b*8];
    float2 t45 = *(const float2*)&g_theta[b*8+4];
    float gx = (float)w*(2.f/255.f) - 1.f;
    float gy = (float)h*(2.f/255.f) - 1.f;
    float tx = gx*t03.x + gy*t03.w + t03.z;
    float ty = gx*t03.y + gy*t45.x + t45.y;
    float xf = 0.5f*((tx+1.f)*255.f);
    float yf = 0.5f*((ty+1.f)*255.f);
    float x0f = floorf(xf), y0f = floorf(yf);
    float x0c = fminf(fmaxf(x0f,0.f),255.f);
    float x1c = fminf(fmaxf(x0f+1.f,0.f),255.f);
    float y0c = fminf(fmaxf(y0f,0.f),255.f);
    float y1c = fminf(fmaxf(y0f+1.f,0.f),255.f);
    float wa=(x1c-xf)*(y1c-yf), wb=(x1c-xf)*(yf-y0c);
    float wc=(xf-x0c)*(y1c-yf), wd=(xf-x0c)*(yf-y0c);
    int xi0=(int)x0c, xi1=(int)x1c, yi0=(int)y0c, yi1=(int)y1c;

    const float* xb = &g_xintp[b*32768];
    int ca = ((yi0>>3)*32 + (xi0>>3))*32;
    int cb = ((yi1>>3)*32 + (xi0>>3))*32;
    int cc = ((yi0>>3)*32 + (xi1>>3))*32;
    int cd = ((yi1>>3)*32 + (xi1>>3))*32;
    float4 Ia = *(const float4*)&xb[ca + q*4];
    float4 Ib = (cb==ca) ? Ia : *(const float4*)&xb[cb + q*4];
    float4 Ic = (cc==ca) ? Ia : *(const float4*)&xb[cc + q*4];
    float4 Id;
    if (cd==cb)      Id = Ib;
    else if (cd==cc) Id = Ic;
    else             Id = *(const float4*)&xb[cd + q*4];

    float4 val;
    val.x = wa*Ia.x + wb*Ib.x + wc*Ic.x + wd*Id.x;
    val.y = wa*Ia.y + wb*Ib.y + wc*Ic.y + wd*Id.y;
    val.z = wa*Ia.z + wb*Ib.z + wc*Ic.z + wd*Id.z;
    val.w = wa*Ia.w + wb*Ib.w + wc*Ic.w + wd*Id.w;

    if (q==0){
        const float* xb0 = x + b*65536;
        val.x = wa*xb0[yi0*256+xi0] + wb*xb0[yi1*256+xi0]
              + wc*xb0[yi0*256+xi1] + wd*xb0[yi1*256+xi1];
    }
    val.x = (val.x>=0.f)? val.x : 0.1f*val.x;
    val.y = (val.y>=0.f)? val.y : 0.1f*val.y;
    val.z = (val.z>=0.f)? val.z : 0.1f*val.z;
    val.w = (val.w>=0.f)? val.w : 0.1f*val.w;
    *(float4*)&out[pix*32 + q*4] = val;
}

extern "C" void kernel_launch(void* const* d_in, const int* in_sizes, int n_in,
                              void* d_out, int out_size)
{
    const float* x   = (const float*)d_in[0];
    const float* c1k = (const float*)d_in[1];
    const float* c1b = (const float*)d_in[2];
    const float* c2k = (const float*)d_in[3];
    const float* c2b = (const float*)d_in[4];
    const float* c3k = (const float*)d_in[5];
    const float* c3b = (const float*)d_in[6];
    const float* bng = (const float*)d_in[7];
    const float* bnb = (const float*)d_in[8];
    const float* bnm = (const float*)d_in[9];
    const float* bnv = (const float*)d_in[10];
    const float* d1k = (const float*)d_in[11];
    const float* d1b = (const float*)d_in[12];
    const float* d2k = (const float*)d_in[13];
    const float* d2b = (const float*)d_in[14];
    const float* d3k = (const float*)d_in[15];
    const float* d3b = (const float*)d_in[16];
    float* out = (float*)d_out;

    dim3 t16(16,16);
    conv1pool_k<<<dim3(8,8,8), t16>>>(x, c1k, c1b, 0);   // launch 1
    conv1pool_k<<<dim3(8,8,8), t16>>>(x, c1k, c1b, 8);   // launch 2
    conv2pool_k<<<dim3(4,4,16), t16>>>(c2k, c2b);        // launch 3
    conv3pool_k<<<dim3(4,4,16), 256>>>(c3k, c3b);        // launch 4 (profiled)
    dense1_k<<<D1_BLKS,256>>>(bng, bnb, bnm, bnv, d1k);  // launch 5
    denserest_k<<<16,256>>>(d1b, d2k, d2b, d3k, d3b);    // launch 6
    sampler_k<<<16*256*256/32, 256>>>(x, out);           // launch 7
}